// round 4
// baseline (speedup 1.0000x reference)
#include <cuda_runtime.h>
#include <math.h>

#define F   128
#define S   10
#define KC  16

#define MAXN 200000
#define MAXB 20000

typedef unsigned long long ull;

// static scratch (allocation-free rule)
__device__ float g_pre[(size_t)MAXN * F];   // t_j * (q_j @ mask)
__device__ float g_ln[MAXN];                // t_j . a_neigh

// ---- packed f32x2 helpers (PTX-only; ptxas won't auto-fuse) ----
__device__ __forceinline__ ull ffma2(ull a, ull b, ull c) {
    ull d; asm("fma.rn.f32x2 %0,%1,%2,%3;" : "=l"(d) : "l"(a), "l"(b), "l"(c)); return d;
}
__device__ __forceinline__ ull fmul2(ull a, ull b) {
    ull d; asm("mul.rn.f32x2 %0,%1,%2;" : "=l"(d) : "l"(a), "l"(b)); return d;
}
__device__ __forceinline__ ull fpack(float a, float b) {
    ull d; asm("mov.b64 %0,{%1,%2};" : "=l"(d) : "f"(a), "f"(b)); return d;
}
__device__ __forceinline__ float2 funpack(ull a) {
    float2 f; asm("mov.b64 {%0,%1},%2;" : "=f"(f.x), "=f"(f.y) : "l"(a)); return f;
}
__device__ __forceinline__ float fsum2(ull a) { float2 f = funpack(a); return f.x + f.y; }

// ---------------------------------------------------------------------------
// Kernel A: per-table-row precompute. grid = ceil(N/128), block = 256.
// Thread = (row r = tid>>1, half h = tid&1). 64 floats of the row live in
// registers; center/mask come from smem as 2-address (dedup) reads.
// ---------------------------------------------------------------------------
__global__ void __launch_bounds__(256, 2)
precompute_kernel(const float* __restrict__ neigh_table,
                  const float* __restrict__ center,
                  const float* __restrict__ cluster_mask,
                  const float* __restrict__ alpha,
                  int N) {
    __shared__ float s_C[2048], s_M[2048], s_an[128], s_c2[16];
    const int tid = threadIdx.x;

    #pragma unroll
    for (int e = tid; e < 512; e += 256) {
        ((float4*)s_C)[e] = ((const float4*)center)[e];
        ((float4*)s_M)[e] = ((const float4*)cluster_mask)[e];
    }
    if (tid < 32) ((float4*)s_an)[tid] = ((const float4*)alpha)[32 + tid];  // a_neigh
    __syncthreads();

    if (tid < KC) {
        float a = 0.f;
        #pragma unroll 8
        for (int f4 = 0; f4 < 32; f4++) {
            float4 c = *(const float4*)&s_C[tid * 128 + f4 * 4];
            a += c.x * c.x + c.y * c.y + c.z * c.z + c.w * c.w;
        }
        s_c2[tid] = a;
    }

    const int r = tid >> 1, h = tid & 1;
    int row = blockIdx.x * 128 + r;
    if (row >= N) row = N - 1;                    // clamp: duplicate rows write
    const size_t base = (size_t)row * F + h * 64; // identical values (safe)

    ulonglong2 xv[16];                            // 64 floats in registers
    const ulonglong2* rp = (const ulonglong2*)(neigh_table + base);
    #pragma unroll
    for (int j = 0; j < 16; j++) xv[j] = rp[j];   // MLP=16 front-batched

    ull n2 = 0ull, ln = 0ull;
    #pragma unroll
    for (int j = 0; j < 16; j++) {
        ulonglong2 a = *(const ulonglong2*)&s_an[h * 64 + j * 4];
        n2 = ffma2(xv[j].x, xv[j].x, n2);  n2 = ffma2(xv[j].y, xv[j].y, n2);
        ln = ffma2(xv[j].x, a.x, ln);      ln = ffma2(xv[j].y, a.y, ln);
    }

    float cross[KC];
    #pragma unroll
    for (int k = 0; k < KC; k++) {
        ull acc = 0ull;
        const float* cb = &s_C[k * 128 + h * 64];
        #pragma unroll
        for (int j = 0; j < 16; j++) {
            ulonglong2 c = *(const ulonglong2*)&cb[j * 4];
            acc = ffma2(xv[j].x, c.x, acc);
            acc = ffma2(xv[j].y, c.y, acc);
        }
        cross[k] = fsum2(acc);
    }

    float n2f = fsum2(n2), lnf = fsum2(ln);
    n2f += __shfl_xor_sync(0xffffffffu, n2f, 1);  // combine halves (lane pair)
    lnf += __shfl_xor_sync(0xffffffffu, lnf, 1);
    #pragma unroll
    for (int k = 0; k < KC; k++)
        cross[k] += __shfl_xor_sync(0xffffffffu, cross[k], 1);
    if (h == 0) g_ln[row] = lnf;

    __syncthreads();                               // s_c2 ready
    float q[KC];
    #pragma unroll
    for (int k = 0; k < KC; k++)
        q[k] = 1.f / (n2f - 2.f * cross[k] + s_c2[k] + 1.f);

    // mask-MM in two 32-float sub-chunks to bound live registers
    #pragma unroll
    for (int sub = 0; sub < 2; sub++) {
        ulonglong2 mv[8];
        #pragma unroll
        for (int j = 0; j < 8; j++) { mv[j].x = 0ull; mv[j].y = 0ull; }
        #pragma unroll
        for (int k = 0; k < KC; k++) {
            ull qk = fpack(q[k], q[k]);
            const float* mb = &s_M[k * 128 + h * 64 + sub * 32];
            #pragma unroll
            for (int j = 0; j < 8; j++) {
                ulonglong2 m = *(const ulonglong2*)&mb[j * 4];
                mv[j].x = ffma2(qk, m.x, mv[j].x);
                mv[j].y = ffma2(qk, m.y, mv[j].y);
            }
        }
        ulonglong2* op = (ulonglong2*)(g_pre + base + sub * 32);
        #pragma unroll
        for (int j = 0; j < 8; j++) {
            ulonglong2 p;
            p.x = fmul2(xv[sub * 8 + j].x, mv[j].x);
            p.y = fmul2(xv[sub * 8 + j].y, mv[j].y);
            op[j] = p;
        }
    }
}

// ---------------------------------------------------------------------------
// Kernel B: fused gather+attention+GEMM. grid = ceil(B/32), block = 256.
// 32-row tiles -> 3 blocks/SM so gather latency overlaps GEMM compute.
// ---------------------------------------------------------------------------
__global__ void __launch_bounds__(256, 3)
fused_kernel(const int* __restrict__ nodes,
             const int* __restrict__ neigh_idx,
             const float* __restrict__ self_table,
             const float* __restrict__ alpha,
             const float* __restrict__ weight,
             float* __restrict__ out, int B) {
    extern __shared__ float sm[];
    float* s_comb  = sm;                 // [32][264]
    float* s_alpha = s_comb + 32 * 264;  // [128]
    float* sAs     = s_alpha + 128;      // [32][36]
    float* sBs     = sAs + 32 * 36;      // [32][132]

    const int tid = threadIdx.x;
    if (tid < 32) ((float4*)s_alpha)[tid] = ((const float4*)alpha)[tid];  // a_self
    __syncthreads();

    // ---- phase 1: gather + attention, 8 threads per row (16 floats each) ----
    {
        const int r = tid >> 3, g = tid & 7;
        int row = blockIdx.x * 32 + r;
        if (row >= B) row = B - 1;
        const int node = nodes[row];
        const float4* sp = (const float4*)(self_table + (size_t)node * F + g * 16);
        float4 sf[4];
        float lp = 0.f;
        #pragma unroll
        for (int j = 0; j < 4; j++) {
            sf[j] = sp[j];
            float4 av = *(const float4*)&s_alpha[g * 16 + j * 4];
            lp += sf[j].x * av.x + sf[j].y * av.y + sf[j].z * av.z + sf[j].w * av.w;
        }
        lp += __shfl_xor_sync(0xffffffffu, lp, 1);
        lp += __shfl_xor_sync(0xffffffffu, lp, 2);
        lp += __shfl_xor_sync(0xffffffffu, lp, 4);

        int ji[S];
        float att[S], asum = 0.f;
        #pragma unroll
        for (int s = 0; s < S; s++) ji[s] = neigh_idx[row * S + s];
        #pragma unroll
        for (int s = 0; s < S; s++) {
            float l = fmaxf(lp + g_ln[ji[s]], 0.f);
            att[s] = __expf(l);
            asum += att[s];
        }
        const float inv = 1.f / asum;
        float4 agg[4];
        #pragma unroll
        for (int j = 0; j < 4; j++) agg[j] = make_float4(0.f, 0.f, 0.f, 0.f);
        #pragma unroll
        for (int s = 0; s < S; s++) {
            const float w = att[s] * inv;
            const float4* pp = (const float4*)(g_pre + (size_t)ji[s] * F + g * 16);
            #pragma unroll
            for (int j = 0; j < 4; j++) {
                float4 v = pp[j];
                agg[j].x += w * v.x;  agg[j].y += w * v.y;
                agg[j].z += w * v.z;  agg[j].w += w * v.w;
            }
        }
        #pragma unroll
        for (int j = 0; j < 4; j++) {
            *(float4*)&s_comb[r * 264 + g * 16 + j * 4]       = sf[j];
            *(float4*)&s_comb[r * 264 + 128 + g * 16 + j * 4] = agg[j];
        }
    }
    __syncthreads();

    // ---- phase 2: out = relu(comb @ W^T), thread tile 2 rows x 8 cols ----
    const int tx = tid & 15;          // 16 col-groups x 8 cols
    const int ty = tid >> 4;          // 16 row-groups x 2 rows
    const int m0 = blockIdx.x * 32;
    ull acc[2][4];
    #pragma unroll
    for (int mm = 0; mm < 2; mm++)
        #pragma unroll
        for (int nn = 0; nn < 4; nn++) acc[mm][nn] = 0ull;

    #pragma unroll 1
    for (int kc = 0; kc < 2 * F; kc += 32) {
        {   // stage A^T: 32 rows x 32 k, one float4 + 4 STS per thread
            int m = tid >> 3, k4 = tid & 7;
            float4 v = *(const float4*)&s_comb[m * 264 + kc + k4 * 4];
            sAs[(k4 * 4 + 0) * 36 + m] = v.x;  sAs[(k4 * 4 + 1) * 36 + m] = v.y;
            sAs[(k4 * 4 + 2) * 36 + m] = v.z;  sAs[(k4 * 4 + 3) * 36 + m] = v.w;
        }
        #pragma unroll
        for (int it = 0; it < 4; it++) {   // stage W^T: 128 rows x 32 k
            int e = it * 256 + tid;
            int rr = e >> 3, k4 = e & 7;
            float4 v = *(const float4*)&weight[rr * 256 + kc + k4 * 4];
            sBs[(k4 * 4 + 0) * 132 + rr] = v.x;  sBs[(k4 * 4 + 1) * 132 + rr] = v.y;
            sBs[(k4 * 4 + 2) * 132 + rr] = v.z;  sBs[(k4 * 4 + 3) * 132 + rr] = v.w;
        }
        __syncthreads();
        #pragma unroll
        for (int k = 0; k < 32; k++) {
            float2 a2 = *(const float2*)&sAs[k * 36 + ty * 2];       // 2-addr bcast
            ulonglong2 b0 = *(const ulonglong2*)&sBs[k * 132 + tx * 8];
            ulonglong2 b1 = *(const ulonglong2*)&sBs[k * 132 + tx * 8 + 4];
            ull a0 = fpack(a2.x, a2.x), a1 = fpack(a2.y, a2.y);
            acc[0][0] = ffma2(a0, b0.x, acc[0][0]);
            acc[0][1] = ffma2(a0, b0.y, acc[0][1]);
            acc[0][2] = ffma2(a0, b1.x, acc[0][2]);
            acc[0][3] = ffma2(a0, b1.y, acc[0][3]);
            acc[1][0] = ffma2(a1, b0.x, acc[1][0]);
            acc[1][1] = ffma2(a1, b0.y, acc[1][1]);
            acc[1][2] = ffma2(a1, b1.x, acc[1][2]);
            acc[1][3] = ffma2(a1, b1.y, acc[1][3]);
        }
        __syncthreads();
    }

    #pragma unroll
    for (int mm = 0; mm < 2; mm++) {
        int m = m0 + ty * 2 + mm;
        if (m < B) {
            float2 p0 = funpack(acc[mm][0]);
            float2 p1 = funpack(acc[mm][1]);
            float2 p2 = funpack(acc[mm][2]);
            float2 p3 = funpack(acc[mm][3]);
            float4 o0, o1;
            o0.x = fmaxf(p0.x, 0.f);  o0.y = fmaxf(p0.y, 0.f);
            o0.z = fmaxf(p1.x, 0.f);  o0.w = fmaxf(p1.y, 0.f);
            o1.x = fmaxf(p2.x, 0.f);  o1.y = fmaxf(p2.y, 0.f);
            o1.z = fmaxf(p3.x, 0.f);  o1.w = fmaxf(p3.y, 0.f);
            *(float4*)&out[(size_t)m * F + tx * 8]     = o0;
            *(float4*)&out[(size_t)m * F + tx * 8 + 4] = o1;
        }
    }
}

#define B_SMEM ((32 * 264 + 128 + 32 * 36 + 32 * 132) * 4)

// ---------------------------------------------------------------------------
extern "C" void kernel_launch(void* const* d_in, const int* in_sizes, int n_in,
                              void* d_out, int out_size) {
    const int*   nodes        = (const int*)d_in[0];
    const int*   neigh_idx    = (const int*)d_in[1];
    const float* self_table   = (const float*)d_in[2];
    const float* neigh_table  = (const float*)d_in[3];
    const float* center       = (const float*)d_in[4];
    const float* cluster_mask = (const float*)d_in[5];
    const float* weight       = (const float*)d_in[6];
    const float* alpha        = (const float*)d_in[7];
    float* out = (float*)d_out;

    int B = in_sizes[0];
    int N = in_sizes[3] / F;

    cudaFuncSetAttribute(fused_kernel, cudaFuncAttributeMaxDynamicSharedMemorySize, B_SMEM);

    precompute_kernel<<<(N + 127) / 128, 256>>>(neigh_table, center, cluster_mask, alpha, N);
    fused_kernel<<<(B + 31) / 32, 256, B_SMEM>>>(nodes, neigh_idx, self_table, alpha, weight, out, B);
}

// round 5
// speedup vs baseline: 1.6530x; 1.6530x over previous
#include <cuda_runtime.h>
#include <math.h>

#define F   128
#define S   10
#define KC  16
#define MAXN 200000
#define MAXB 20000

typedef unsigned long long ull;

// static scratch (allocation-free rule)
__device__ float g_pre[(size_t)MAXN * F];      // t_j * (q_j @ mask)
__device__ float g_ln[MAXN];                   // t_j . a_neigh
__device__ float g_comb[(size_t)MAXB * 2 * F]; // [self | neigh_agg]
__device__ float g_wT[256 * 128];              // weight transposed [k][e]

// ---- packed f32x2 helpers (PTX-only; ptxas won't auto-fuse) ----
__device__ __forceinline__ ull ffma2(ull a, ull b, ull c) {
    ull d; asm("fma.rn.f32x2 %0,%1,%2,%3;" : "=l"(d) : "l"(a), "l"(b), "l"(c)); return d;
}
__device__ __forceinline__ ull fmul2(ull a, ull b) {
    ull d; asm("mul.rn.f32x2 %0,%1,%2;" : "=l"(d) : "l"(a), "l"(b)); return d;
}
__device__ __forceinline__ ull fpack(float a, float b) {
    ull d; asm("mov.b64 %0,{%1,%2};" : "=l"(d) : "f"(a), "f"(b)); return d;
}
__device__ __forceinline__ float2 funpack(ull a) {
    float2 f; asm("mov.b64 {%0,%1},%2;" : "=f"(f.x), "=f"(f.y) : "l"(a)); return f;
}
__device__ __forceinline__ float fsum2(ull a) { float2 f = funpack(a); return f.x + f.y; }

// ---------------------------------------------------------------------------
// Kernel A: per-table-row precompute. grid = ceil(N/128), block = 256.
// Thread = (row = tid>>1, half = tid&1). Tile stride 136 words, half offset
// 68 words -> lane banks {8r, 8r+4, ...} = conflict-free bijection for
// LDS.128; center/mask reads are 2-address broadcasts on disjoint banks.
// ---------------------------------------------------------------------------
#define TS  136
#define HOF 68

__global__ void __launch_bounds__(256, 2)
precompute_kernel(const float* __restrict__ neigh_table,
                  const float* __restrict__ center,
                  const float* __restrict__ cluster_mask,
                  const float* __restrict__ alpha,
                  int N) {
    extern __shared__ float sm[];
    float* s_T  = sm;                 // [128][TS]
    float* s_C  = s_T + 128 * TS;     // [16][TS] (half layout)
    float* s_M  = s_C + KC * TS;      // [16][TS]
    float* s_an = s_M + KC * TS;      // [TS]
    float* s_c2 = s_an + TS;          // [16]

    const int tid = threadIdx.x;
    const int rowbase = blockIdx.x * 128;

    // consts: [k][f] -> [k*TS + (f>>6)*HOF + (f&63)]
    #pragma unroll
    for (int e = tid; e < 512; e += 256) {                // 512 float4
        int k = e >> 5, c4 = e & 31;
        int dst = k * TS + (c4 >> 4) * HOF + (c4 & 15) * 4;
        *(float4*)&s_C[dst] = ((const float4*)center)[e];
        *(float4*)&s_M[dst] = ((const float4*)cluster_mask)[e];
    }
    if (tid < 32) {
        int dst = (tid >> 4) * HOF + (tid & 15) * 4;
        *(float4*)&s_an[dst] = ((const float4*)alpha)[32 + tid];  // a_neigh
    }

    // tile load: coalesced LDG.128, row-clamped
    #pragma unroll
    for (int it = 0; it < 16; it++) {
        int e = it * 256 + tid;
        int r = e >> 5, c4 = e & 31;
        int grow = min(rowbase + r, N - 1);
        float4 v = *(const float4*)&neigh_table[(size_t)grow * F + c4 * 4];
        *(float4*)&s_T[r * TS + (c4 >> 4) * HOF + (c4 & 15) * 4] = v;
    }
    __syncthreads();

    if (tid < KC) {                    // c2
        float a = 0.f;
        #pragma unroll
        for (int hh = 0; hh < 2; hh++)
            #pragma unroll 4
            for (int j = 0; j < 16; j++) {
                float4 c = *(const float4*)&s_C[tid * TS + hh * HOF + j * 4];
                a += c.x * c.x + c.y * c.y + c.z * c.z + c.w * c.w;
            }
        s_c2[tid] = a;
    }

    const int rl = tid >> 1, h = tid & 1;
    const int grow = min(rowbase + rl, N - 1);
    const float* xb = &s_T[rl * TS + h * HOF];
    const float* ab = &s_an[h * HOF];

    // ---- cross GEMM + n2/ln, f32x2, 16 independent accumulator chains ----
    ull acc[KC];
    #pragma unroll
    for (int k = 0; k < KC; k++) acc[k] = 0ull;
    ull n2 = 0ull, ln = 0ull;

    #pragma unroll 4
    for (int ch = 0; ch < 16; ch++) {
        ulonglong2 x = *(const ulonglong2*)&xb[ch * 4];
        ulonglong2 a = *(const ulonglong2*)&ab[ch * 4];
        n2 = ffma2(x.x, x.x, n2);  n2 = ffma2(x.y, x.y, n2);
        ln = ffma2(x.x, a.x, ln);  ln = ffma2(x.y, a.y, ln);
        #pragma unroll
        for (int k = 0; k < KC; k++) {
            ulonglong2 c = *(const ulonglong2*)&s_C[k * TS + h * HOF + ch * 4];
            acc[k] = ffma2(x.x, c.x, acc[k]);
            acc[k] = ffma2(x.y, c.y, acc[k]);
        }
    }

    float n2f = fsum2(n2), lnf = fsum2(ln);
    n2f += __shfl_xor_sync(0xffffffffu, n2f, 1);
    lnf += __shfl_xor_sync(0xffffffffu, lnf, 1);
    if (h == 0) g_ln[grow] = lnf;

    float crs[KC];
    #pragma unroll
    for (int k = 0; k < KC; k++) {
        crs[k] = fsum2(acc[k]);
        crs[k] += __shfl_xor_sync(0xffffffffu, crs[k], 1);
    }

    __syncthreads();                   // s_c2 ready
    ull qq[KC];
    #pragma unroll
    for (int k = 0; k < KC; k++) {
        float q = 1.f / (n2f - 2.f * crs[k] + s_c2[k] + 1.f);
        qq[k] = fpack(q, q);
    }

    // ---- mask-MM + elementwise write ----
    float* op = g_pre + (size_t)grow * F + h * 64;
    #pragma unroll 4
    for (int ch = 0; ch < 16; ch++) {
        ull mx = 0ull, my = 0ull;
        #pragma unroll
        for (int k = 0; k < KC; k++) {
            ulonglong2 m = *(const ulonglong2*)&s_M[k * TS + h * HOF + ch * 4];
            mx = ffma2(qq[k], m.x, mx);
            my = ffma2(qq[k], m.y, my);
        }
        ulonglong2 x = *(const ulonglong2*)&xb[ch * 4];
        ulonglong2 p;
        p.x = fmul2(x.x, mx);
        p.y = fmul2(x.y, my);
        *(ulonglong2*)&op[ch * 4] = p;
    }
}

#define A_SMEM ((128 * TS + 2 * KC * TS + TS + KC) * 4)

// ---------------------------------------------------------------------------
// Kernel W: transpose weight[128][256] -> g_wT[256][128] (one-time, tiny)
// ---------------------------------------------------------------------------
__global__ void transpose_w(const float* __restrict__ weight) {
    int idx = blockIdx.x * 256 + threadIdx.x;      // 32768 total
    int k = idx >> 7, n = idx & 127;
    g_wT[idx] = weight[n * 256 + k];
}

// ---------------------------------------------------------------------------
// Kernel B: gather + attention. grid = ceil(B/32), block = 256, 8 thr/row.
// Pure memory machine: high warp count, 40 independent LDG.128 per thread.
// ---------------------------------------------------------------------------
__global__ void __launch_bounds__(256)
gather_kernel(const int* __restrict__ nodes,
              const int* __restrict__ neigh_idx,
              const float* __restrict__ self_table,
              const float* __restrict__ alpha,
              int B) {
    __shared__ float s_alpha[128];
    const int tid = threadIdx.x;
    if (tid < 32) ((float4*)s_alpha)[tid] = ((const float4*)alpha)[tid];  // a_self
    __syncthreads();

    const int r = tid >> 3, g = tid & 7;            // 8 lanes per row
    const int row = min(blockIdx.x * 32 + r, B - 1);
    const int node = nodes[row];

    const float4* sp = (const float4*)(self_table + (size_t)node * F + g * 16);
    float4 sf[4];
    float lp = 0.f;
    #pragma unroll
    for (int j = 0; j < 4; j++) {
        sf[j] = sp[j];
        float4 av = *(const float4*)&s_alpha[g * 16 + j * 4];
        lp += sf[j].x * av.x + sf[j].y * av.y + sf[j].z * av.z + sf[j].w * av.w;
    }
    lp += __shfl_xor_sync(0xffffffffu, lp, 1);
    lp += __shfl_xor_sync(0xffffffffu, lp, 2);
    lp += __shfl_xor_sync(0xffffffffu, lp, 4);

    int ji[S];
    #pragma unroll
    for (int s = 0; s < S; s++) ji[s] = neigh_idx[row * S + s];
    float att[S], asum = 0.f;
    #pragma unroll
    for (int s = 0; s < S; s++) {
        float l = fmaxf(lp + g_ln[ji[s]], 0.f);
        att[s] = __expf(l);
        asum += att[s];
    }
    const float inv = 1.f / asum;

    float4 agg[4];
    #pragma unroll
    for (int j = 0; j < 4; j++) agg[j] = make_float4(0.f, 0.f, 0.f, 0.f);
    #pragma unroll
    for (int s = 0; s < S; s++) {
        const float w = att[s] * inv;
        const float4* pp = (const float4*)(g_pre + (size_t)ji[s] * F + g * 16);
        #pragma unroll
        for (int j = 0; j < 4; j++) {
            float4 v = pp[j];
            agg[j].x += w * v.x;  agg[j].y += w * v.y;
            agg[j].z += w * v.z;  agg[j].w += w * v.w;
        }
    }

    float* cb = g_comb + (size_t)row * 256;
    #pragma unroll
    for (int j = 0; j < 4; j++) {
        *(float4*)&cb[g * 16 + j * 4]       = sf[j];
        *(float4*)&cb[128 + g * 16 + j * 4] = agg[j];
    }
}

// ---------------------------------------------------------------------------
// Kernel C: out = relu(comb @ W^T). 64x128 tile, BK=32, 256 thr.
// f32x2 along M: A m-pairs load natively (no packing); 4 b-dups per k.
// ---------------------------------------------------------------------------
__global__ void __launch_bounds__(256)
gemm_kernel(float* __restrict__ out, int B) {
    __shared__ float As[32 * 68];     // [k][m]
    __shared__ float Bs[32 * 132];    // [k][n]

    const int tid = threadIdx.x;
    const int tx = tid & 31, ty = tid >> 5;    // warp shares ty -> A broadcast
    const int m0 = blockIdx.x * 64;

    ull acc[4][4];                             // [m-pair][n]
    #pragma unroll
    for (int mp = 0; mp < 4; mp++)
        #pragma unroll
        for (int n = 0; n < 4; n++) acc[mp][n] = 0ull;

    #pragma unroll 1
    for (int kc = 0; kc < 256; kc += 32) {
        #pragma unroll
        for (int it = 0; it < 2; it++) {       // A: 64m x 32k -> As[k][m]
            int e = it * 256 + tid;
            int m = e >> 3, k4 = e & 7;
            int gm = min(m0 + m, B - 1);
            float4 v = *(const float4*)&g_comb[(size_t)gm * 256 + kc + k4 * 4];
            As[(k4 * 4 + 0) * 68 + m] = v.x;  As[(k4 * 4 + 1) * 68 + m] = v.y;
            As[(k4 * 4 + 2) * 68 + m] = v.z;  As[(k4 * 4 + 3) * 68 + m] = v.w;
        }
        #pragma unroll
        for (int it = 0; it < 4; it++) {       // B: 32k x 128n from g_wT
            int e = it * 256 + tid;
            int k = e >> 5, n4 = e & 31;
            *(float4*)&Bs[k * 132 + n4 * 4] =
                *(const float4*)&g_wT[(kc + k) * 128 + n4 * 4];
        }
        __syncthreads();

        #pragma unroll
        for (int k = 0; k < 32; k++) {
            ulonglong2 a01 = *(const ulonglong2*)&As[k * 68 + ty * 8];      // bcast
            ulonglong2 a23 = *(const ulonglong2*)&As[k * 68 + ty * 8 + 4];  // bcast
            float4 b = *(const float4*)&Bs[k * 132 + tx * 4];
            ull b0 = fpack(b.x, b.x), b1 = fpack(b.y, b.y);
            ull b2 = fpack(b.z, b.z), b3 = fpack(b.w, b.w);
            acc[0][0] = ffma2(a01.x, b0, acc[0][0]);
            acc[0][1] = ffma2(a01.x, b1, acc[0][1]);
            acc[0][2] = ffma2(a01.x, b2, acc[0][2]);
            acc[0][3] = ffma2(a01.x, b3, acc[0][3]);
            acc[1][0] = ffma2(a01.y, b0, acc[1][0]);
            acc[1][1] = ffma2(a01.y, b1, acc[1][1]);
            acc[1][2] = ffma2(a01.y, b2, acc[1][2]);
            acc[1][3] = ffma2(a01.y, b3, acc[1][3]);
            acc[2][0] = ffma2(a23.x, b0, acc[2][0]);
            acc[2][1] = ffma2(a23.x, b1, acc[2][1]);
            acc[2][2] = ffma2(a23.x, b2, acc[2][2]);
            acc[2][3] = ffma2(a23.x, b3, acc[2][3]);
            acc[3][0] = ffma2(a23.y, b0, acc[3][0]);
            acc[3][1] = ffma2(a23.y, b1, acc[3][1]);
            acc[3][2] = ffma2(a23.y, b2, acc[3][2]);
            acc[3][3] = ffma2(a23.y, b3, acc[3][3]);
        }
        __syncthreads();
    }

    #pragma unroll
    for (int mp = 0; mp < 4; mp++) {
        float2 p0 = funpack(acc[mp][0]);
        float2 p1 = funpack(acc[mp][1]);
        float2 p2 = funpack(acc[mp][2]);
        float2 p3 = funpack(acc[mp][3]);
        int m = m0 + ty * 8 + mp * 2;
        if (m < B) {
            float4 o;
            o.x = fmaxf(p0.x, 0.f);  o.y = fmaxf(p1.x, 0.f);
            o.z = fmaxf(p2.x, 0.f);  o.w = fmaxf(p3.x, 0.f);
            *(float4*)&out[(size_t)m * F + tx * 4] = o;
        }
        if (m + 1 < B) {
            float4 o;
            o.x = fmaxf(p0.y, 0.f);  o.y = fmaxf(p1.y, 0.f);
            o.z = fmaxf(p2.y, 0.f);  o.w = fmaxf(p3.y, 0.f);
            *(float4*)&out[(size_t)(m + 1) * F + tx * 4] = o;
        }
    }
}

// ---------------------------------------------------------------------------
extern "C" void kernel_launch(void* const* d_in, const int* in_sizes, int n_in,
                              void* d_out, int out_size) {
    const int*   nodes        = (const int*)d_in[0];
    const int*   neigh_idx    = (const int*)d_in[1];
    const float* self_table   = (const float*)d_in[2];
    const float* neigh_table  = (const float*)d_in[3];
    const float* center       = (const float*)d_in[4];
    const float* cluster_mask = (const float*)d_in[5];
    const float* weight       = (const float*)d_in[6];
    const float* alpha        = (const float*)d_in[7];
    float* out = (float*)d_out;

    int B = in_sizes[0];
    int N = in_sizes[3] / F;

    cudaFuncSetAttribute(precompute_kernel,
                         cudaFuncAttributeMaxDynamicSharedMemorySize, A_SMEM);

    transpose_w<<<128, 256>>>(weight);
    precompute_kernel<<<(N + 127) / 128, 256, A_SMEM>>>(neigh_table, center,
                                                        cluster_mask, alpha, N);
    gather_kernel<<<(B + 31) / 32, 256>>>(nodes, neigh_idx, self_table, alpha, B);
    gemm_kernel<<<(B + 63) / 64, 256>>>(out, B);
}